// round 12
// baseline (speedup 1.0000x reference)
#include <cuda_runtime.h>
#include <math.h>
#include <mma.h>
using namespace nvcuda;

#define NN 50000
#define IN_DIM 78
#define HEADS 10
#define CH 78
#define HC 780
#define HC2 390           // float2 slots per node row
#define EE 400000
#define E2 (EE + NN)      // 450000 edges incl self loops
#define BB 256
#define NEG 0.2f
#define NBLK 196          // ceil(NN/256)

// ---------------- scratch (static device memory; no allocs allowed) ----------------
__device__ float g_bufA[(size_t)NN * HC];   // xl -> (reused) h2 = h1 @ W_gcn
__device__ float g_bufB[(size_t)NN * HC];   // xr -> (reused) gcn output (relu'd)
__device__ float g_bufC[(size_t)NN * HC];   // h1 = elu(GAT out + bias1)
__device__ float g_score[(size_t)E2 * HEADS];
__device__ int   g_src[E2], g_dst[E2], g_csrc[E2];
__device__ int   g_deg[NN], g_fill[NN];
__device__ int   g_rowstart[NN + 1];
__device__ int   g_scan[NN];
__device__ int   g_bsum[256], g_boff[256];
__device__ float g_dinv[NN];
__device__ int   g_bstart[BB + 1];
__device__ int   g_flags[2];   // [0]=edge_index is int64, [1]=batch is int64

// ---------------- helpers ----------------
__device__ __forceinline__ int ld_idx(const void* p, long long i, int is64) {
    if (is64) return (int)((const long long*)p)[i];
    return ((const int*)p)[i];
}
__device__ __forceinline__ void cpasync16(void* dst, const void* src, bool pred) {
    unsigned d = (unsigned)__cvta_generic_to_shared(dst);
    int sz = pred ? 16 : 0;
    asm volatile("cp.async.cg.shared.global [%0], [%1], 16, %2;\n" :: "r"(d), "l"(src), "r"(sz));
}
__device__ __forceinline__ void cpasync8(void* dst, const void* src, bool pred) {
    unsigned d = (unsigned)__cvta_generic_to_shared(dst);
    int sz = pred ? 8 : 0;
    asm volatile("cp.async.ca.shared.global [%0], [%1], 8, %2;\n" :: "r"(d), "l"(src), "r"(sz));
}

// ---------------- dtype detection ----------------
__global__ void detect_kernel(const void* ei, const void* batch) {
    int lane = threadIdx.x;  // 32 threads
    int nz_e = 0, nz_b = 0;
    for (int j = 0; j < 4; j++) {
        long long k = (long long)lane * 4 + j;             // 0..127
        long long p = (((2LL * EE - 2) * k) / 127) | 1;    // odd, < 2E
        if (((const int*)ei)[p] != 0) nz_e = 1;
        long long q = (long long)NN - 256 + 2 * k + 1;     // odd, near end
        if (((const int*)batch)[q] != 0) nz_b = 1;
    }
    nz_e = __any_sync(0xffffffffu, nz_e);
    nz_b = __any_sync(0xffffffffu, nz_b);
    if (lane == 0) { g_flags[0] = nz_e ? 0 : 1; g_flags[1] = nz_b ? 0 : 1; }
}

// ---------------- init ----------------
__global__ void init_kernel() {
    int i = blockIdx.x * 256 + threadIdx.x;
    if (i < NN) { g_deg[i] = 0; g_fill[i] = 0; }
}

// ---------------- edge conversion + degree histogram ----------------
__global__ void conv_kernel(const void* __restrict__ ei) {
    int e = blockIdx.x * 256 + threadIdx.x;
    if (e >= E2) return;
    int is64 = g_flags[0];
    int s, d;
    if (e < EE) { s = ld_idx(ei, e, is64); d = ld_idx(ei, (long long)EE + e, is64); }
    else { s = d = e - EE; }
    g_src[e] = s; g_dst[e] = d;
    atomicAdd(&g_deg[d], 1);
}

// ---------------- prefix sum over degrees (3 kernels) ----------------
__global__ void scan1_kernel() {
    __shared__ int s[256];
    int i = blockIdx.x * 256 + threadIdx.x;
    int v = (i < NN) ? g_deg[i] : 0;
    s[threadIdx.x] = v;
    for (int off = 1; off < 256; off <<= 1) {
        __syncthreads();
        int t = (threadIdx.x >= off) ? s[threadIdx.x - off] : 0;
        __syncthreads();
        s[threadIdx.x] += t;
    }
    __syncthreads();
    if (i < NN) g_scan[i] = s[threadIdx.x];
    if (threadIdx.x == 255) g_bsum[blockIdx.x] = s[255];
}
__global__ void scan2_kernel() {
    __shared__ int s[256];
    int tid = threadIdx.x;
    int v = (tid < NBLK) ? g_bsum[tid] : 0;
    s[tid] = v;
    for (int off = 1; off < 256; off <<= 1) {
        __syncthreads();
        int t = (tid >= off) ? s[tid - off] : 0;
        __syncthreads();
        s[tid] += t;
    }
    __syncthreads();
    g_boff[tid] = s[tid] - v;   // exclusive
}
__global__ void scan3_kernel() {
    int i = blockIdx.x * 256 + threadIdx.x;
    if (i < NN) g_rowstart[i] = g_boff[i >> 8] + g_scan[i] - g_deg[i];
    if (i == 0) g_rowstart[NN] = E2;
}

__global__ void dinv_kernel() {
    int i = blockIdx.x * 256 + threadIdx.x;
    if (i >= NN) return;
    g_dinv[i] = rsqrtf(fmaxf((float)g_deg[i], 1e-12f));
}

// ---------------- CSR scatter ----------------
__global__ void scatter_kernel() {
    int e = blockIdx.x * 256 + threadIdx.x;
    if (e >= E2) return;
    int d = g_dst[e];
    int pos = g_rowstart[d] + atomicAdd(&g_fill[d], 1);
    g_csrc[pos] = g_src[e];
}

// ---------------- TF32 tensor-core GEMM, 3-stage cp.async, 64x64 warp tiles ----------------
// C[M,N] = A[M,K] @ B[K,N], row-major. 128x128 block tile, BK=32.
// 4 warps (128 threads) in 2(M)x2(N); warp tile 64x64 (4x4 m16n16k8 frags).
#define GBM 128
#define GBN 128
#define GBK 32
#define APAD 4
#define BPAD 4
#define ASZF (GBM * (GBK + APAD))     // 4608 floats
#define BSZF (GBK * (GBN + BPAD))     // 4224 floats
#define STGF (ASZF + BSZF)            // 8832 floats per stage
#define NSTG 3
#define GEMM_SMEM (NSTG * STGF * 4)   // 105984 bytes
#define GEMM_T 128

extern __shared__ float dynsmem[];

__global__ __launch_bounds__(GEMM_T) void tf32gemm_kernel(
    const float* __restrict__ A, const float* __restrict__ B, float* __restrict__ C,
    int M, int N, int K)
{
    int tid = threadIdx.x;
    int wid = tid >> 5;
    int lane = tid & 31;
    int row0 = blockIdx.y * GBM, col0 = blockIdx.x * GBN;
    int wm = (wid >> 1) * 64;   // warp M offset
    int wn = (wid & 1) * 64;    // warp N offset

    const int T = (K + GBK - 1) / GBK;

    // closed-form per-thread copy coordinates (128 threads)
    // A: 128x32 floats = 2048 8B chunks, 16/thread: row=(tid>>4)+8i, col=(tid&15)*2
    const int a_c = (tid & 15) * 2, a_r = tid >> 4;
    // B: 32x128 floats = 1024 16B chunks, 8/thread: row=(tid>>5)+4i, col=(tid&31)*4
    const int b_c = (tid & 31) * 4, b_r = tid >> 5;

    auto load_tile = [&](int t, int s) {
        int k0 = t * GBK;
        float* As = dynsmem + s * STGF;
        float* Bs = dynsmem + s * STGF + ASZF;
#pragma unroll
        for (int i = 0; i < 16; i++) {
            int r = a_r + 8 * i;
            int gr = row0 + r, gc = k0 + a_c;
            cpasync8(As + r * (GBK + APAD) + a_c,
                     A + (long long)gr * K + gc, gr < M && gc < K);
        }
#pragma unroll
        for (int i = 0; i < 8; i++) {
            int r = b_r + 4 * i;
            int gr = k0 + r, gc = col0 + b_c;
            cpasync16(Bs + r * (GBN + BPAD) + b_c,
                      B + (long long)gr * N + gc, gr < K && gc < N);
        }
        asm volatile("cp.async.commit_group;\n" ::: "memory");
    };

    wmma::fragment<wmma::accumulator, 16, 16, 8, float> acc[4][4];
#pragma unroll
    for (int i = 0; i < 4; i++)
#pragma unroll
        for (int j = 0; j < 4; j++) wmma::fill_fragment(acc[i][j], 0.0f);

    load_tile(0, 0);
    if (T > 1) load_tile(1, 1);

    for (int t = 0; t < T; t++) {
        if (t + 2 < T) {
            load_tile(t + 2, (t + 2) % NSTG);
            asm volatile("cp.async.wait_group 2;\n" ::: "memory");
        } else if (t + 1 < T) {
            asm volatile("cp.async.wait_group 1;\n" ::: "memory");
        } else {
            asm volatile("cp.async.wait_group 0;\n" ::: "memory");
        }
        __syncthreads();

        int s = t % NSTG;
        float (*As)[GBK + APAD] = (float(*)[GBK + APAD])(dynsmem + s * STGF);
        float (*Bs)[GBN + BPAD] = (float(*)[GBN + BPAD])(dynsmem + s * STGF + ASZF);

#pragma unroll
        for (int kk = 0; kk < GBK / 8; kk++) {
            wmma::fragment<wmma::matrix_a, 16, 16, 8, wmma::precision::tf32, wmma::row_major> af[4];
            wmma::fragment<wmma::matrix_b, 16, 16, 8, wmma::precision::tf32, wmma::row_major> bf[4];
#pragma unroll
            for (int i = 0; i < 4; i++) {
                wmma::load_matrix_sync(af[i], &As[wm + 16 * i][kk * 8], GBK + APAD);
#pragma unroll
                for (int q = 0; q < af[i].num_elements; q++)
                    af[i].x[q] = wmma::__float_to_tf32(af[i].x[q]);
            }
#pragma unroll
            for (int j = 0; j < 4; j++) {
                wmma::load_matrix_sync(bf[j], &Bs[kk * 8][wn + 16 * j], GBN + BPAD);
#pragma unroll
                for (int q = 0; q < bf[j].num_elements; q++)
                    bf[j].x[q] = wmma::__float_to_tf32(bf[j].x[q]);
            }
#pragma unroll
            for (int i = 0; i < 4; i++)
#pragma unroll
                for (int j = 0; j < 4; j++)
                    wmma::mma_sync(acc[i][j], af[i], bf[j], acc[i][j]);
        }
        __syncthreads();
    }

    // store
    if (row0 + GBM <= M && col0 + GBN <= N) {
#pragma unroll
        for (int i = 0; i < 4; i++)
#pragma unroll
            for (int j = 0; j < 4; j++)
                wmma::store_matrix_sync(&C[(long long)(row0 + wm + 16 * i) * N + col0 + wn + 16 * j],
                                        acc[i][j], N, wmma::mem_row_major);
    } else {
        // stage through smem (pipeline buffers are dead now)
        float* stg = dynsmem + wid * (16 * 20);
#pragma unroll
        for (int i = 0; i < 4; i++)
#pragma unroll
            for (int j = 0; j < 4; j++) {
                wmma::store_matrix_sync(stg, acc[i][j], 20, wmma::mem_row_major);
                __syncwarp();
                int r0 = row0 + wm + 16 * i, c0 = col0 + wn + 16 * j;
                for (int t = lane; t < 256; t += 32) {
                    int r = t >> 4, c = t & 15;
                    if (r0 + r < M && c0 + c < N)
                        C[(long long)(r0 + r) * N + c0 + c] = stg[r * 20 + c];
                }
                __syncwarp();
            }
    }
}

// ---------------- fused GATv2 (two-pass): warp per destination node ----------------
__global__ __launch_bounds__(256) void gat_kernel(const float* __restrict__ att,
                                                  const float* __restrict__ bias1) {
    __shared__ float2 attS[HC2];
    int tid = threadIdx.x;
    for (int i = tid; i < HC2; i += 256) attS[i] = ((const float2*)att)[i];
    __syncthreads();

    int dst = blockIdx.x * 8 + (tid >> 5);
    if (dst >= NN) return;
    int lane = tid & 31;
    int p0 = g_rowstart[dst], p1 = g_rowstart[dst + 1];

    const float2* xl2 = (const float2*)g_bufA;
    const float2* xr2 = (const float2*)g_bufB;
    size_t dbase = (size_t)dst * HC2;

    float2 xr0[HEADS], xr1[HEADS];
#pragma unroll
    for (int h = 0; h < HEADS; h++) {
        xr0[h] = xr2[dbase + h * 39 + lane];
        if (lane < 7) xr1[h] = xr2[dbase + h * 39 + 32 + lane];
    }

    // ---- pass A: scores ----
    for (int p = p0; p < p1; p++) {
        int src = g_csrc[p];
        size_t sb = (size_t)src * HC2;
        float sc = 0.f;
#pragma unroll
        for (int h = 0; h < HEADS; h++) {
            float2 v = xl2[sb + h * 39 + lane];
            float2 a = attS[h * 39 + lane];
            float e0 = v.x + xr0[h].x; e0 = e0 > 0.f ? e0 : NEG * e0;
            float e1 = v.y + xr0[h].y; e1 = e1 > 0.f ? e1 : NEG * e1;
            float t = e0 * a.x + e1 * a.y;
            if (lane < 7) {
                float2 v1 = xl2[sb + h * 39 + 32 + lane];
                float2 a1 = attS[h * 39 + 32 + lane];
                float f0 = v1.x + xr1[h].x; f0 = f0 > 0.f ? f0 : NEG * f0;
                float f1 = v1.y + xr1[h].y; f1 = f1 > 0.f ? f1 : NEG * f1;
                t += f0 * a1.x + f1 * a1.y;
            }
#pragma unroll
            for (int o = 16; o; o >>= 1) t += __shfl_xor_sync(0xffffffffu, t, o);
            if (lane == h) sc = t;
        }
        if (lane < HEADS) g_score[(size_t)p * HEADS + lane] = sc;
    }

    // ---- softmax stats (lane h owns head h) ----
    float m = -3.4e38f, rden = 0.f;
    if (lane < HEADS) {
        for (int p = p0; p < p1; p++) m = fmaxf(m, g_score[(size_t)p * HEADS + lane]);
        float ssum = 0.f;
        for (int p = p0; p < p1; p++) ssum += expf(g_score[(size_t)p * HEADS + lane] - m);
        rden = 1.f / ssum;
    }

    // ---- pass B: weighted aggregation ----
    float2 acc0[HEADS], acc1[HEADS];
#pragma unroll
    for (int h = 0; h < HEADS; h++) { acc0[h] = make_float2(0.f, 0.f); acc1[h] = make_float2(0.f, 0.f); }
    for (int p = p0; p < p1; p++) {
        int src = g_csrc[p];
        size_t sb = (size_t)src * HC2;
        float a = (lane < HEADS) ? expf(g_score[(size_t)p * HEADS + lane] - m) * rden : 0.f;
#pragma unroll
        for (int h = 0; h < HEADS; h++) {
            float al = __shfl_sync(0xffffffffu, a, h);
            float2 v = xl2[sb + h * 39 + lane];
            acc0[h].x += al * v.x; acc0[h].y += al * v.y;
            if (lane < 7) {
                float2 v1 = xl2[sb + h * 39 + 32 + lane];
                acc1[h].x += al * v1.x; acc1[h].y += al * v1.y;
            }
        }
    }

    // ---- epilogue: h1 = elu(acc + bias1) ----
    float2* o2 = (float2*)g_bufC;
    const float2* b2 = (const float2*)bias1;
#pragma unroll
    for (int h = 0; h < HEADS; h++) {
        int j = h * 39 + lane;
        float2 bb = b2[j];
        float u0 = acc0[h].x + bb.x; u0 = u0 > 0.f ? u0 : expm1f(u0);
        float u1 = acc0[h].y + bb.y; u1 = u1 > 0.f ? u1 : expm1f(u1);
        o2[dbase + j] = make_float2(u0, u1);
        if (lane < 7) {
            int j1 = h * 39 + 32 + lane;
            float2 bb1 = b2[j1];
            float w0 = acc1[h].x + bb1.x; w0 = w0 > 0.f ? w0 : expm1f(w0);
            float w1 = acc1[h].y + bb1.y; w1 = w1 > 0.f ? w1 : expm1f(w1);
            o2[dbase + j1] = make_float2(w0, w1);
        }
    }
}

// ---------------- fused GCN: warp per destination node (+bias, relu) ----------------
__global__ __launch_bounds__(256) void gcn_kernel(const float* __restrict__ bias_gcn) {
    int dst = blockIdx.x * 8 + (threadIdx.x >> 5);
    if (dst >= NN) return;
    int lane = threadIdx.x & 31;
    int p0 = g_rowstart[dst], p1 = g_rowstart[dst + 1];
    float di = g_dinv[dst];
    const float2* h2 = (const float2*)g_bufA;

    float2 acc[13];
#pragma unroll
    for (int k = 0; k < 13; k++) acc[k] = make_float2(0.f, 0.f);

    for (int p = p0; p < p1; p++) {
        int src = g_csrc[p];
        float nrm = di * g_dinv[src];
        size_t sb = (size_t)src * HC2;
#pragma unroll
        for (int k = 0; k < 13; k++) {
            int idx = lane + 32 * k;
            if (idx < HC2) {
                float2 v = h2[sb + idx];
                acc[k].x += nrm * v.x; acc[k].y += nrm * v.y;
            }
        }
    }
    float2* o2 = (float2*)g_bufB;
    const float2* b2 = (const float2*)bias_gcn;
    size_t dbase = (size_t)dst * HC2;
#pragma unroll
    for (int k = 0; k < 13; k++) {
        int idx = lane + 32 * k;
        if (idx < HC2) {
            float2 bb = b2[idx];
            o2[dbase + idx] = make_float2(fmaxf(acc[k].x + bb.x, 0.f),
                                          fmaxf(acc[k].y + bb.y, 0.f));
        }
    }
}

// ---------------- batch segment boundaries (batch is sorted) ----------------
__global__ void bstart_kernel(const void* __restrict__ batch) {
    int i = blockIdx.x * 256 + threadIdx.x;
    if (i >= NN) return;
    int is64 = g_flags[1];
    int b = ld_idx(batch, i, is64);
    if (i == 0) { for (int bb = 0; bb <= b; bb++) g_bstart[bb] = 0; }
    else {
        int pb = ld_idx(batch, i - 1, is64);
        for (int bb = pb + 1; bb <= b; bb++) g_bstart[bb] = i;
    }
    if (i == NN - 1) { for (int bb = b + 1; bb <= BB; bb++) g_bstart[bb] = NN; }
}

// ---------------- segmented pooling: block per batch ----------------
__global__ __launch_bounds__(256) void pool_kernel(float* __restrict__ out) {
    int b = blockIdx.x;
    int tid = threadIdx.x;
    int lo = g_bstart[b], hi = g_bstart[b + 1];
    float inv = 1.f / fmaxf((float)(hi - lo), 1.f);
    for (int c = tid; c < HC; c += 256) {
        float mx = 0.f, sm = 0.f;
        for (int n = lo; n < hi; n++) {
            float v = g_bufB[(size_t)n * HC + c];
            mx = fmaxf(mx, v);
            sm += v;
        }
        out[(size_t)b * 2 * HC + c] = mx;
        out[(size_t)b * 2 * HC + HC + c] = sm * inv;
    }
}

// ---------------- launch ----------------
extern "C" void kernel_launch(void* const* d_in, const int* in_sizes, int n_in,
                              void* d_out, int out_size) {
    const float* x        = (const float*)d_in[0];
    const void*  ei       = d_in[1];
    const void*  batch    = d_in[2];
    const float* W_l      = (const float*)d_in[3];
    const float* W_r      = (const float*)d_in[4];
    const float* att      = (const float*)d_in[5];
    const float* bias1    = (const float*)d_in[6];
    const float* W_gcn    = (const float*)d_in[7];
    const float* bias_gcn = (const float*)d_in[8];
    float* out = (float*)d_out;

    float *pA, *pB, *pC;
    cudaGetSymbolAddress((void**)&pA, g_bufA);
    cudaGetSymbolAddress((void**)&pB, g_bufB);
    cudaGetSymbolAddress((void**)&pC, g_bufC);

    cudaFuncSetAttribute(tf32gemm_kernel, cudaFuncAttributeMaxDynamicSharedMemorySize, GEMM_SMEM);

    const int T = 256;
    const int GE = (E2 + T - 1) / T;
    const int GN = NBLK;

    detect_kernel<<<1, 32>>>(ei, batch);
    init_kernel<<<GN, T>>>();
    conv_kernel<<<GE, T>>>(ei);
    scan1_kernel<<<GN, T>>>();
    scan2_kernel<<<1, T>>>();
    scan3_kernel<<<GN, T>>>();
    dinv_kernel<<<GN, T>>>();
    scatter_kernel<<<GE, T>>>();

    dim3 gmm((HC + GBN - 1) / GBN, (NN + GBM - 1) / GBM);   // (7, 391)
    tf32gemm_kernel<<<gmm, GEMM_T, GEMM_SMEM>>>(x, W_l, pA, NN, HC, IN_DIM);   // xl -> bufA
    tf32gemm_kernel<<<gmm, GEMM_T, GEMM_SMEM>>>(x, W_r, pB, NN, HC, IN_DIM);   // xr -> bufB

    gat_kernel<<<(NN * 32) / T, T>>>(att, bias1);                              // h1 -> bufC

    tf32gemm_kernel<<<gmm, GEMM_T, GEMM_SMEM>>>(pC, W_gcn, pA, NN, HC, HC);    // h2 -> bufA

    gcn_kernel<<<(NN * 32) / T, T>>>(bias_gcn);                                // relu(gcn) -> bufB

    bstart_kernel<<<GN, T>>>(batch);
    pool_kernel<<<BB, T>>>(out);
}

// round 13
// speedup vs baseline: 1.4008x; 1.4008x over previous
#include <cuda_runtime.h>
#include <math.h>
#include <mma.h>
using namespace nvcuda;

#define NN 50000
#define IN_DIM 78
#define HEADS 10
#define CH 78
#define HC 780
#define HC2 390           // float2 slots per node row
#define EE 400000
#define E2 (EE + NN)      // 450000 edges incl self loops
#define BB 256
#define NEG 0.2f
#define NBLK 196          // ceil(NN/256)

// ---------------- scratch (static device memory; no allocs allowed) ----------------
__device__ float g_bufA[(size_t)NN * HC];   // xl -> (reused) h2 = h1 @ W_gcn
__device__ float g_bufB[(size_t)NN * HC];   // xr -> (reused) gcn output (relu'd)
__device__ float g_bufC[(size_t)NN * HC];   // h1 = elu(GAT out + bias1), tf32-rounded
__device__ float g_score[(size_t)E2 * HEADS]; // rounded-x before GAT, then edge scores
__device__ float g_wlr[2 * IN_DIM * HC];    // tf32-rounded W_l | W_r
__device__ float g_wgcn[HC * HC];           // tf32-rounded W_gcn
__device__ int   g_src[E2], g_dst[E2], g_csrc[E2];
__device__ int   g_deg[NN], g_fill[NN];
__device__ int   g_rowstart[NN + 1];
__device__ int   g_scan[NN];
__device__ int   g_bsum[256], g_boff[256];
__device__ float g_dinv[NN];
__device__ int   g_bstart[BB + 1];
__device__ int   g_flags[2];   // [0]=edge_index is int64, [1]=batch is int64

// ---------------- helpers ----------------
__device__ __forceinline__ int ld_idx(const void* p, long long i, int is64) {
    if (is64) return (int)((const long long*)p)[i];
    return ((const int*)p)[i];
}
__device__ __forceinline__ float to_tf32(float x) {
    float r; asm("cvt.rna.tf32.f32 %0, %1;" : "=f"(r) : "f"(x)); return r;
}
__device__ __forceinline__ void cpasync16(void* dst, const void* src, bool pred) {
    unsigned d = (unsigned)__cvta_generic_to_shared(dst);
    int sz = pred ? 16 : 0;
    asm volatile("cp.async.cg.shared.global [%0], [%1], 16, %2;\n" :: "r"(d), "l"(src), "r"(sz));
}
__device__ __forceinline__ void cpasync8(void* dst, const void* src, bool pred) {
    unsigned d = (unsigned)__cvta_generic_to_shared(dst);
    int sz = pred ? 8 : 0;
    asm volatile("cp.async.ca.shared.global [%0], [%1], 8, %2;\n" :: "r"(d), "l"(src), "r"(sz));
}

// ---------------- dtype detection ----------------
__global__ void detect_kernel(const void* ei, const void* batch) {
    int lane = threadIdx.x;  // 32 threads
    int nz_e = 0, nz_b = 0;
    for (int j = 0; j < 4; j++) {
        long long k = (long long)lane * 4 + j;             // 0..127
        long long p = (((2LL * EE - 2) * k) / 127) | 1;    // odd, < 2E
        if (((const int*)ei)[p] != 0) nz_e = 1;
        long long q = (long long)NN - 256 + 2 * k + 1;     // odd, near end
        if (((const int*)batch)[q] != 0) nz_b = 1;
    }
    nz_e = __any_sync(0xffffffffu, nz_e);
    nz_b = __any_sync(0xffffffffu, nz_b);
    if (lane == 0) { g_flags[0] = nz_e ? 0 : 1; g_flags[1] = nz_b ? 0 : 1; }
}

// ---------------- init ----------------
__global__ void init_kernel() {
    int i = blockIdx.x * 256 + threadIdx.x;
    if (i < NN) { g_deg[i] = 0; g_fill[i] = 0; }
}

// ---------------- tf32 pre-rounding of GEMM operands ----------------
// x -> g_score (reused as rounded-x until gat_kernel), W_l|W_r -> g_wlr, W_gcn -> g_wgcn
__global__ void round_kernel(const float* __restrict__ x,
                             const float* __restrict__ W_l,
                             const float* __restrict__ W_r,
                             const float* __restrict__ W_gcn) {
    int i = blockIdx.x * 256 + threadIdx.x;
    int total = NN * IN_DIM;               // 3.9M
    if (i < total) g_score[i] = to_tf32(x[i]);
    if (i < IN_DIM * HC) {
        g_wlr[i] = to_tf32(W_l[i]);
        g_wlr[IN_DIM * HC + i] = to_tf32(W_r[i]);
    }
    if (i < HC * HC) g_wgcn[i] = to_tf32(W_gcn[i]);
}

// ---------------- edge conversion + degree histogram ----------------
__global__ void conv_kernel(const void* __restrict__ ei) {
    int e = blockIdx.x * 256 + threadIdx.x;
    if (e >= E2) return;
    int is64 = g_flags[0];
    int s, d;
    if (e < EE) { s = ld_idx(ei, e, is64); d = ld_idx(ei, (long long)EE + e, is64); }
    else { s = d = e - EE; }
    g_src[e] = s; g_dst[e] = d;
    atomicAdd(&g_deg[d], 1);
}

// ---------------- prefix sum over degrees (3 kernels) ----------------
__global__ void scan1_kernel() {
    __shared__ int s[256];
    int i = blockIdx.x * 256 + threadIdx.x;
    int v = (i < NN) ? g_deg[i] : 0;
    s[threadIdx.x] = v;
    for (int off = 1; off < 256; off <<= 1) {
        __syncthreads();
        int t = (threadIdx.x >= off) ? s[threadIdx.x - off] : 0;
        __syncthreads();
        s[threadIdx.x] += t;
    }
    __syncthreads();
    if (i < NN) g_scan[i] = s[threadIdx.x];
    if (threadIdx.x == 255) g_bsum[blockIdx.x] = s[255];
}
__global__ void scan2_kernel() {
    __shared__ int s[256];
    int tid = threadIdx.x;
    int v = (tid < NBLK) ? g_bsum[tid] : 0;
    s[tid] = v;
    for (int off = 1; off < 256; off <<= 1) {
        __syncthreads();
        int t = (tid >= off) ? s[tid - off] : 0;
        __syncthreads();
        s[tid] += t;
    }
    __syncthreads();
    g_boff[tid] = s[tid] - v;   // exclusive
}
__global__ void scan3_kernel() {
    int i = blockIdx.x * 256 + threadIdx.x;
    if (i < NN) g_rowstart[i] = g_boff[i >> 8] + g_scan[i] - g_deg[i];
    if (i == 0) g_rowstart[NN] = E2;
}

__global__ void dinv_kernel() {
    int i = blockIdx.x * 256 + threadIdx.x;
    if (i >= NN) return;
    g_dinv[i] = rsqrtf(fmaxf((float)g_deg[i], 1e-12f));
}

// ---------------- CSR scatter ----------------
__global__ void scatter_kernel() {
    int e = blockIdx.x * 256 + threadIdx.x;
    if (e >= E2) return;
    int d = g_dst[e];
    int pos = g_rowstart[d] + atomicAdd(&g_fill[d], 1);
    g_csrc[pos] = g_src[e];
}

// ---------------- TF32 tensor-core GEMM, 3-stage cp.async pipeline ----------------
// Operands MUST be pre-rounded to tf32 (no per-fragment conversion here).
// C[M,N] = A[M,K] @ B[K,N], row-major. 128x128 block tile, BK=32.
// 8 warps (256 threads) in 4(M)x2(N); warp tile 32x64 (2x4 m16n16k8 frags).
#define GBM 128
#define GBN 128
#define GBK 32
#define APAD 4
#define BPAD 4
#define ASZF (GBM * (GBK + APAD))     // 4608 floats
#define BSZF (GBK * (GBN + BPAD))     // 4224 floats
#define STGF (ASZF + BSZF)            // 8832 floats per stage
#define NSTG 3
#define GEMM_SMEM (NSTG * STGF * 4)   // 105984 bytes

extern __shared__ float dynsmem[];

__global__ __launch_bounds__(256) void tf32gemm_kernel(
    const float* __restrict__ A, const float* __restrict__ B, float* __restrict__ C,
    int M, int N, int K)
{
    int tid = threadIdx.x;
    int wid = tid >> 5;
    int lane = tid & 31;
    int row0 = blockIdx.y * GBM, col0 = blockIdx.x * GBN;
    int wm = (wid >> 1) * 32;
    int wn = (wid & 1) * 64;

    const int T = (K + GBK - 1) / GBK;

    // per-thread copy coordinates
    // A: 128x32 floats as 2048 8B chunks; 8 per thread
    int ar[8], ac[8];
#pragma unroll
    for (int i = 0; i < 8; i++) {
        int c = tid + i * 256;
        ar[i] = c >> 4; ac[i] = (c & 15) * 2;
    }
    // B: 32x128 floats as 1024 16B chunks; 4 per thread
    int br[4], bc[4];
#pragma unroll
    for (int i = 0; i < 4; i++) {
        int c = tid + i * 256;
        br[i] = c >> 5; bc[i] = (c & 31) * 4;
    }

    auto load_tile = [&](int t, int s) {
        int k0 = t * GBK;
        float* As = dynsmem + s * STGF;
        float* Bs = dynsmem + s * STGF + ASZF;
#pragma unroll
        for (int i = 0; i < 8; i++) {
            int gr = row0 + ar[i], gc = k0 + ac[i];
            cpasync8(As + ar[i] * (GBK + APAD) + ac[i],
                     A + (long long)gr * K + gc, gr < M && gc < K);
        }
#pragma unroll
        for (int i = 0; i < 4; i++) {
            int gr = k0 + br[i], gc = col0 + bc[i];
            cpasync16(Bs + br[i] * (GBN + BPAD) + bc[i],
                      B + (long long)gr * N + gc, gr < K && gc < N);
        }
        asm volatile("cp.async.commit_group;\n" ::: "memory");
    };

    wmma::fragment<wmma::accumulator, 16, 16, 8, float> acc[2][4];
#pragma unroll
    for (int i = 0; i < 2; i++)
#pragma unroll
        for (int j = 0; j < 4; j++) wmma::fill_fragment(acc[i][j], 0.0f);

    load_tile(0, 0);
    if (T > 1) load_tile(1, 1);

    for (int t = 0; t < T; t++) {
        if (t + 2 < T) {
            load_tile(t + 2, (t + 2) % NSTG);
            asm volatile("cp.async.wait_group 2;\n" ::: "memory");
        } else if (t + 1 < T) {
            asm volatile("cp.async.wait_group 1;\n" ::: "memory");
        } else {
            asm volatile("cp.async.wait_group 0;\n" ::: "memory");
        }
        __syncthreads();

        int s = t % NSTG;
        float (*As)[GBK + APAD] = (float(*)[GBK + APAD])(dynsmem + s * STGF);
        float (*Bs)[GBN + BPAD] = (float(*)[GBN + BPAD])(dynsmem + s * STGF + ASZF);

#pragma unroll
        for (int kk = 0; kk < GBK / 8; kk++) {
            wmma::fragment<wmma::matrix_a, 16, 16, 8, wmma::precision::tf32, wmma::row_major> af[2];
            wmma::fragment<wmma::matrix_b, 16, 16, 8, wmma::precision::tf32, wmma::row_major> bf[4];
#pragma unroll
            for (int i = 0; i < 2; i++)
                wmma::load_matrix_sync(af[i], &As[wm + 16 * i][kk * 8], GBK + APAD);
#pragma unroll
            for (int j = 0; j < 4; j++)
                wmma::load_matrix_sync(bf[j], &Bs[kk * 8][wn + 16 * j], GBN + BPAD);
#pragma unroll
            for (int i = 0; i < 2; i++)
#pragma unroll
                for (int j = 0; j < 4; j++)
                    wmma::mma_sync(acc[i][j], af[i], bf[j], acc[i][j]);
        }
        __syncthreads();
    }

    // store
    if (row0 + GBM <= M && col0 + GBN <= N) {
#pragma unroll
        for (int i = 0; i < 2; i++)
#pragma unroll
            for (int j = 0; j < 4; j++)
                wmma::store_matrix_sync(&C[(long long)(row0 + wm + 16 * i) * N + col0 + wn + 16 * j],
                                        acc[i][j], N, wmma::mem_row_major);
    } else {
        // stage through smem (pipeline buffers are dead now)
        float* stg = dynsmem + wid * (16 * 20);
#pragma unroll
        for (int i = 0; i < 2; i++)
#pragma unroll
            for (int j = 0; j < 4; j++) {
                wmma::store_matrix_sync(stg, acc[i][j], 20, wmma::mem_row_major);
                __syncwarp();
                int r0 = row0 + wm + 16 * i, c0 = col0 + wn + 16 * j;
                for (int t = lane; t < 256; t += 32) {
                    int r = t >> 4, c = t & 15;
                    if (r0 + r < M && c0 + c < N)
                        C[(long long)(r0 + r) * N + c0 + c] = stg[r * 20 + c];
                }
                __syncwarp();
            }
    }
}

// ---------------- fused GATv2 (two-pass): warp per destination node ----------------
__global__ __launch_bounds__(256) void gat_kernel(const float* __restrict__ att,
                                                  const float* __restrict__ bias1) {
    __shared__ float2 attS[HC2];
    int tid = threadIdx.x;
    for (int i = tid; i < HC2; i += 256) attS[i] = ((const float2*)att)[i];
    __syncthreads();

    int dst = blockIdx.x * 8 + (tid >> 5);
    if (dst >= NN) return;
    int lane = tid & 31;
    int p0 = g_rowstart[dst], p1 = g_rowstart[dst + 1];

    const float2* xl2 = (const float2*)g_bufA;
    const float2* xr2 = (const float2*)g_bufB;
    size_t dbase = (size_t)dst * HC2;

    float2 xr0[HEADS], xr1[HEADS];
#pragma unroll
    for (int h = 0; h < HEADS; h++) {
        xr0[h] = xr2[dbase + h * 39 + lane];
        if (lane < 7) xr1[h] = xr2[dbase + h * 39 + 32 + lane];
    }

    // ---- pass A: scores ----
    for (int p = p0; p < p1; p++) {
        int src = g_csrc[p];
        size_t sb = (size_t)src * HC2;
        float sc = 0.f;
#pragma unroll
        for (int h = 0; h < HEADS; h++) {
            float2 v = xl2[sb + h * 39 + lane];
            float2 a = attS[h * 39 + lane];
            float e0 = v.x + xr0[h].x; e0 = e0 > 0.f ? e0 : NEG * e0;
            float e1 = v.y + xr0[h].y; e1 = e1 > 0.f ? e1 : NEG * e1;
            float t = e0 * a.x + e1 * a.y;
            if (lane < 7) {
                float2 v1 = xl2[sb + h * 39 + 32 + lane];
                float2 a1 = attS[h * 39 + 32 + lane];
                float f0 = v1.x + xr1[h].x; f0 = f0 > 0.f ? f0 : NEG * f0;
                float f1 = v1.y + xr1[h].y; f1 = f1 > 0.f ? f1 : NEG * f1;
                t += f0 * a1.x + f1 * a1.y;
            }
#pragma unroll
            for (int o = 16; o; o >>= 1) t += __shfl_xor_sync(0xffffffffu, t, o);
            if (lane == h) sc = t;
        }
        if (lane < HEADS) g_score[(size_t)p * HEADS + lane] = sc;
    }

    // ---- softmax stats (lane h owns head h) ----
    float m = -3.4e38f, rden = 0.f;
    if (lane < HEADS) {
        for (int p = p0; p < p1; p++) m = fmaxf(m, g_score[(size_t)p * HEADS + lane]);
        float ssum = 0.f;
        for (int p = p0; p < p1; p++) ssum += expf(g_score[(size_t)p * HEADS + lane] - m);
        rden = 1.f / ssum;
    }

    // ---- pass B: weighted aggregation ----
    float2 acc0[HEADS], acc1[HEADS];
#pragma unroll
    for (int h = 0; h < HEADS; h++) { acc0[h] = make_float2(0.f, 0.f); acc1[h] = make_float2(0.f, 0.f); }
    for (int p = p0; p < p1; p++) {
        int src = g_csrc[p];
        size_t sb = (size_t)src * HC2;
        float a = (lane < HEADS) ? expf(g_score[(size_t)p * HEADS + lane] - m) * rden : 0.f;
#pragma unroll
        for (int h = 0; h < HEADS; h++) {
            float al = __shfl_sync(0xffffffffu, a, h);
            float2 v = xl2[sb + h * 39 + lane];
            acc0[h].x += al * v.x; acc0[h].y += al * v.y;
            if (lane < 7) {
                float2 v1 = xl2[sb + h * 39 + 32 + lane];
                acc1[h].x += al * v1.x; acc1[h].y += al * v1.y;
            }
        }
    }

    // ---- epilogue: h1 = tf32(elu(acc + bias1)) — pre-rounded for GEMM3 ----
    float2* o2 = (float2*)g_bufC;
    const float2* b2 = (const float2*)bias1;
#pragma unroll
    for (int h = 0; h < HEADS; h++) {
        int j = h * 39 + lane;
        float2 bb = b2[j];
        float u0 = acc0[h].x + bb.x; u0 = u0 > 0.f ? u0 : expm1f(u0);
        float u1 = acc0[h].y + bb.y; u1 = u1 > 0.f ? u1 : expm1f(u1);
        o2[dbase + j] = make_float2(to_tf32(u0), to_tf32(u1));
        if (lane < 7) {
            int j1 = h * 39 + 32 + lane;
            float2 bb1 = b2[j1];
            float w0 = acc1[h].x + bb1.x; w0 = w0 > 0.f ? w0 : expm1f(w0);
            float w1 = acc1[h].y + bb1.y; w1 = w1 > 0.f ? w1 : expm1f(w1);
            o2[dbase + j1] = make_float2(to_tf32(w0), to_tf32(w1));
        }
    }
}

// ---------------- fused GCN: warp per destination node (+bias, relu) ----------------
__global__ __launch_bounds__(256) void gcn_kernel(const float* __restrict__ bias_gcn) {
    int dst = blockIdx.x * 8 + (threadIdx.x >> 5);
    if (dst >= NN) return;
    int lane = threadIdx.x & 31;
    int p0 = g_rowstart[dst], p1 = g_rowstart[dst + 1];
    float di = g_dinv[dst];
    const float2* h2 = (const float2*)g_bufA;

    float2 acc[13];
#pragma unroll
    for (int k = 0; k < 13; k++) acc[k] = make_float2(0.f, 0.f);

    for (int p = p0; p < p1; p++) {
        int src = g_csrc[p];
        float nrm = di * g_dinv[src];
        size_t sb = (size_t)src * HC2;
#pragma unroll
        for (int k = 0; k < 13; k++) {
            int idx = lane + 32 * k;
            if (idx < HC2) {
                float2 v = h2[sb + idx];
                acc[k].x += nrm * v.x; acc[k].y += nrm * v.y;
            }
        }
    }
    float2* o2 = (float2*)g_bufB;
    const float2* b2 = (const float2*)bias_gcn;
    size_t dbase = (size_t)dst * HC2;
#pragma unroll
    for (int k = 0; k < 13; k++) {
        int idx = lane + 32 * k;
        if (idx < HC2) {
            float2 bb = b2[idx];
            o2[dbase + idx] = make_float2(fmaxf(acc[k].x + bb.x, 0.f),
                                          fmaxf(acc[k].y + bb.y, 0.f));
        }
    }
}

// ---------------- batch segment boundaries (batch is sorted) ----------------
__global__ void bstart_kernel(const void* __restrict__ batch) {
    int i = blockIdx.x * 256 + threadIdx.x;
    if (i >= NN) return;
    int is64 = g_flags[1];
    int b = ld_idx(batch, i, is64);
    if (i == 0) { for (int bb = 0; bb <= b; bb++) g_bstart[bb] = 0; }
    else {
        int pb = ld_idx(batch, i - 1, is64);
        for (int bb = pb + 1; bb <= b; bb++) g_bstart[bb] = i;
    }
    if (i == NN - 1) { for (int bb = b + 1; bb <= BB; bb++) g_bstart[bb] = NN; }
}

// ---------------- segmented pooling: block per batch ----------------
__global__ __launch_bounds__(256) void pool_kernel(float* __restrict__ out) {
    int b = blockIdx.x;
    int tid = threadIdx.x;
    int lo = g_bstart[b], hi = g_bstart[b + 1];
    float inv = 1.f / fmaxf((float)(hi - lo), 1.f);
    for (int c = tid; c < HC; c += 256) {
        float mx = 0.f, sm = 0.f;
        for (int n = lo; n < hi; n++) {
            float v = g_bufB[(size_t)n * HC + c];
            mx = fmaxf(mx, v);
            sm += v;
        }
        out[(size_t)b * 2 * HC + c] = mx;
        out[(size_t)b * 2 * HC + HC + c] = sm * inv;
    }
}

// ---------------- launch ----------------
extern "C" void kernel_launch(void* const* d_in, const int* in_sizes, int n_in,
                              void* d_out, int out_size) {
    const float* x        = (const float*)d_in[0];
    const void*  ei       = d_in[1];
    const void*  batch    = d_in[2];
    const float* W_l      = (const float*)d_in[3];
    const float* W_r      = (const float*)d_in[4];
    const float* att      = (const float*)d_in[5];
    const float* bias1    = (const float*)d_in[6];
    const float* W_gcn    = (const float*)d_in[7];
    const float* bias_gcn = (const float*)d_in[8];
    float* out = (float*)d_out;

    float *pA, *pB, *pC, *pX, *pWlr, *pWg;
    cudaGetSymbolAddress((void**)&pA, g_bufA);
    cudaGetSymbolAddress((void**)&pB, g_bufB);
    cudaGetSymbolAddress((void**)&pC, g_bufC);
    cudaGetSymbolAddress((void**)&pX, g_score);   // rounded-x lives here until GAT
    cudaGetSymbolAddress((void**)&pWlr, g_wlr);
    cudaGetSymbolAddress((void**)&pWg, g_wgcn);

    cudaFuncSetAttribute(tf32gemm_kernel, cudaFuncAttributeMaxDynamicSharedMemorySize, GEMM_SMEM);

    const int T = 256;
    const int GE = (E2 + T - 1) / T;
    const int GN = NBLK;

    detect_kernel<<<1, 32>>>(ei, batch);
    init_kernel<<<GN, T>>>();
    round_kernel<<<(NN * IN_DIM + T - 1) / T, T>>>(x, W_l, W_r, W_gcn);
    conv_kernel<<<GE, T>>>(ei);
    scan1_kernel<<<GN, T>>>();
    scan2_kernel<<<1, T>>>();
    scan3_kernel<<<GN, T>>>();
    dinv_kernel<<<GN, T>>>();
    scatter_kernel<<<GE, T>>>();

    dim3 gmm((HC + GBN - 1) / GBN, (NN + GBM - 1) / GBM);   // (7, 391)
    tf32gemm_kernel<<<gmm, T, GEMM_SMEM>>>(pX, pWlr, pA, NN, HC, IN_DIM);              // xl -> bufA
    tf32gemm_kernel<<<gmm, T, GEMM_SMEM>>>(pX, pWlr + IN_DIM * HC, pB, NN, HC, IN_DIM); // xr -> bufB

    gat_kernel<<<(NN * 32) / T, T>>>(att, bias1);                          // h1 -> bufC (tf32-rounded)

    tf32gemm_kernel<<<gmm, T, GEMM_SMEM>>>(pC, pWg, pA, NN, HC, HC);       // h2 -> bufA

    gcn_kernel<<<(NN * 32) / T, T>>>(bias_gcn);                            // relu(gcn) -> bufB

    bstart_kernel<<<GN, T>>>(batch);
    pool_kernel<<<BB, T>>>(out);
}